// round 1
// baseline (speedup 1.0000x reference)
#include <cuda_runtime.h>

// FlowDE: Heun integration of a flow ODE whose drift needs an attention-like
// softmax field per evaluation.
//   logits[n,m] = scale * (x_n . x0_m) - c2 * ||x0_m||^2      (row-const term cancels)
//   qt = softmax(logits) @ x0
//   G  = ((1-S0)*x - qt) / sigma(t)
// 8 G-evaluations total (t = 1, 7/8, ..., 1/8).
//
// Per eval: K1 (GEMM1 -> logits in g_S), K2 (row max/sum), K3 (K-split GEMM2
// of exp(S-max) @ x0), K4 (combine + Heun state update). All fp32.

#define Nn 4096
#define Mm 4096
#define Dd 64
#define Tt 8
#define Hh 0.125f
#define S0c 0.001f
#define KSPLIT 4

__device__ float g_xt[Nn * Dd];
__device__ float g_xeff[Nn * Dd];
__device__ float g_G1[Nn * Dd];
__device__ float g_x0sq[Mm];
__device__ float g_S[(size_t)Nn * Mm];     // 64 MB logits scratch (fits L2)
__device__ float g_rmax[Nn];
__device__ float g_rsum[Nn];
__device__ float g_qpart[KSPLIT * Nn * Dd];

// ---------------------------------------------------------------------------
// Init: xt = xeff = z; x0sq[m] = ||x0_m||^2
// ---------------------------------------------------------------------------
__global__ void k_init(const float* __restrict__ z, const float* __restrict__ x0) {
    int idx = blockIdx.x * blockDim.x + threadIdx.x;
    if (idx < Nn * Dd) {
        float v = z[idx];
        g_xt[idx] = v;
        g_xeff[idx] = v;
    }
    if (idx < Mm) {
        const float4* r = reinterpret_cast<const float4*>(x0 + idx * Dd);
        float s = 0.f;
#pragma unroll
        for (int i = 0; i < Dd / 4; i++) {
            float4 v = r[i];
            s += v.x * v.x + v.y * v.y + v.z * v.z + v.w * v.w;
        }
        g_x0sq[idx] = s;
    }
}

// ---------------------------------------------------------------------------
// K1: logits = scale * (xeff @ x0^T) - c2 * x0sq.  Block tile 128x128, K=64.
// 256 threads, 8x8 micro-tile. Shared tiles stored K-major (transposed).
// ---------------------------------------------------------------------------
__global__ __launch_bounds__(256) void k_gemm1(const float* __restrict__ x0,
                                               float scale, float c2) {
    __shared__ float XT[32][132];
    __shared__ float X0T[32][132];

    const int tid = threadIdx.x;
    const int n0 = blockIdx.y * 128;
    const int m0 = blockIdx.x * 128;
    const int tn = tid / 16;   // 0..15 -> 8 rows each
    const int tm = tid % 16;   // 0..15 -> 8 cols each
    const int lr = tid / 8;    // loader: 0..31
    const int lq = tid % 8;    // loader: 0..7 (float4 column group)

    float c[8][8];
#pragma unroll
    for (int i = 0; i < 8; i++)
#pragma unroll
        for (int j = 0; j < 8; j++) c[i][j] = 0.f;

    for (int kk = 0; kk < 2; kk++) {
        __syncthreads();
#pragma unroll
        for (int it = 0; it < 4; it++) {
            int r = lr + 32 * it;
            float4 va = *reinterpret_cast<const float4*>(
                &g_xeff[(n0 + r) * Dd + kk * 32 + 4 * lq]);
            XT[4 * lq + 0][r] = va.x;
            XT[4 * lq + 1][r] = va.y;
            XT[4 * lq + 2][r] = va.z;
            XT[4 * lq + 3][r] = va.w;
            float4 vb = *reinterpret_cast<const float4*>(
                &x0[(m0 + r) * Dd + kk * 32 + 4 * lq]);
            X0T[4 * lq + 0][r] = vb.x;
            X0T[4 * lq + 1][r] = vb.y;
            X0T[4 * lq + 2][r] = vb.z;
            X0T[4 * lq + 3][r] = vb.w;
        }
        __syncthreads();
#pragma unroll
        for (int k = 0; k < 32; k++) {
            float4 a0 = *reinterpret_cast<const float4*>(&XT[k][8 * tn]);
            float4 a1 = *reinterpret_cast<const float4*>(&XT[k][8 * tn + 4]);
            float4 b0 = *reinterpret_cast<const float4*>(&X0T[k][8 * tm]);
            float4 b1 = *reinterpret_cast<const float4*>(&X0T[k][8 * tm + 4]);
            float a[8] = {a0.x, a0.y, a0.z, a0.w, a1.x, a1.y, a1.z, a1.w};
            float b[8] = {b0.x, b0.y, b0.z, b0.w, b1.x, b1.y, b1.z, b1.w};
#pragma unroll
            for (int i = 0; i < 8; i++)
#pragma unroll
                for (int j = 0; j < 8; j++) c[i][j] += a[i] * b[j];
        }
    }

    float bias[8];
#pragma unroll
    for (int j = 0; j < 8; j++) bias[j] = -c2 * g_x0sq[m0 + 8 * tm + j];

#pragma unroll
    for (int i = 0; i < 8; i++) {
        size_t off = (size_t)(n0 + 8 * tn + i) * Mm + m0 + 8 * tm;
        float4 w0 = make_float4(fmaf(scale, c[i][0], bias[0]),
                                fmaf(scale, c[i][1], bias[1]),
                                fmaf(scale, c[i][2], bias[2]),
                                fmaf(scale, c[i][3], bias[3]));
        float4 w1 = make_float4(fmaf(scale, c[i][4], bias[4]),
                                fmaf(scale, c[i][5], bias[5]),
                                fmaf(scale, c[i][6], bias[6]),
                                fmaf(scale, c[i][7], bias[7]));
        *reinterpret_cast<float4*>(&g_S[off]) = w0;
        *reinterpret_cast<float4*>(&g_S[off + 4]) = w1;
    }
}

// ---------------------------------------------------------------------------
// K2: per-row online (max, sum of exp) over 4096 logits. One block per row.
// ---------------------------------------------------------------------------
__global__ void k_rowstats() {
    const int n = blockIdx.x;
    const float4* row = reinterpret_cast<const float4*>(&g_S[(size_t)n * Mm]);
    float mx = -1e30f, sm = 0.f;
    for (int i = threadIdx.x; i < Mm / 4; i += 128) {
        float4 v = row[i];
        float vals[4] = {v.x, v.y, v.z, v.w};
#pragma unroll
        for (int j = 0; j < 4; j++) {
            float x = vals[j];
            if (x > mx) {
                sm = sm * __expf(mx - x) + 1.f;
                mx = x;
            } else {
                sm += __expf(x - mx);
            }
        }
    }
#pragma unroll
    for (int o = 16; o; o >>= 1) {
        float mx2 = __shfl_xor_sync(0xffffffffu, mx, o);
        float sm2 = __shfl_xor_sync(0xffffffffu, sm, o);
        float m = fmaxf(mx, mx2);
        sm = sm * __expf(mx - m) + sm2 * __expf(mx2 - m);
        mx = m;
    }
    __shared__ float smx[4], ssm[4];
    int w = threadIdx.x >> 5;
    if ((threadIdx.x & 31) == 0) { smx[w] = mx; ssm[w] = sm; }
    __syncthreads();
    if (threadIdx.x == 0) {
        mx = smx[0]; sm = ssm[0];
#pragma unroll
        for (int w2 = 1; w2 < 4; w2++) {
            float m = fmaxf(mx, smx[w2]);
            sm = sm * __expf(mx - m) + ssm[w2] * __expf(smx[w2] - m);
            mx = m;
        }
        g_rmax[n] = mx;
        g_rsum[n] = sm;
    }
}

// ---------------------------------------------------------------------------
// K3: qpart[s] = exp(S - rmax) @ x0 over m-range [s*1024, (s+1)*1024).
// Block tile 128n x 64d, k-tiles of 32. 256 threads, 8x4 micro-tile.
// ---------------------------------------------------------------------------
__global__ __launch_bounds__(256) void k_gemm2(const float* __restrict__ x0) {
    __shared__ float PT[32][132];     // exp(logit - rmax), k-major
    __shared__ float X0s[32][Dd];     // x0 tile, row-major
    __shared__ float rm[128];

    const int tid = threadIdx.x;
    const int s = blockIdx.x;          // k-split index
    const int n0 = blockIdx.y * 128;
    const int tn = tid / 16;           // 0..15 -> 8 n-rows
    const int td = tid % 16;           // 0..15 -> 4 d-cols
    const int lr = tid / 8;            // loader 0..31
    const int lq = tid % 8;            // loader 0..7

    if (tid < 128) rm[tid] = g_rmax[n0 + tid];

    float c[8][4];
#pragma unroll
    for (int i = 0; i < 8; i++)
#pragma unroll
        for (int j = 0; j < 4; j++) c[i][j] = 0.f;

    for (int kt = 0; kt < Mm / KSPLIT; kt += 32) {
        const int mb = s * (Mm / KSPLIT) + kt;
        __syncthreads();
#pragma unroll
        for (int it = 0; it < 4; it++) {
            int r = lr + 32 * it;
            float4 v = *reinterpret_cast<const float4*>(
                &g_S[(size_t)(n0 + r) * Mm + mb + 4 * lq]);
            float rmax = rm[r];
            PT[4 * lq + 0][r] = __expf(v.x - rmax);
            PT[4 * lq + 1][r] = __expf(v.y - rmax);
            PT[4 * lq + 2][r] = __expf(v.z - rmax);
            PT[4 * lq + 3][r] = __expf(v.w - rmax);
        }
#pragma unroll
        for (int it = 0; it < 2; it++) {
            int v = tid + 256 * it;          // 0..511 float4 slots (32x16)
            int rr = v / 16, c4 = v % 16;
            *reinterpret_cast<float4*>(&X0s[rr][4 * c4]) =
                *reinterpret_cast<const float4*>(&x0[(mb + rr) * Dd + 4 * c4]);
        }
        __syncthreads();
#pragma unroll
        for (int k = 0; k < 32; k++) {
            float4 a0 = *reinterpret_cast<const float4*>(&PT[k][8 * tn]);
            float4 a1 = *reinterpret_cast<const float4*>(&PT[k][8 * tn + 4]);
            float4 b = *reinterpret_cast<const float4*>(&X0s[k][4 * td]);
            float a[8] = {a0.x, a0.y, a0.z, a0.w, a1.x, a1.y, a1.z, a1.w};
            float bb[4] = {b.x, b.y, b.z, b.w};
#pragma unroll
            for (int i = 0; i < 8; i++)
#pragma unroll
                for (int j = 0; j < 4; j++) c[i][j] += a[i] * bb[j];
        }
    }

#pragma unroll
    for (int i = 0; i < 8; i++) {
        int off = s * Nn * Dd + (n0 + 8 * tn + i) * Dd + 4 * td;
        *reinterpret_cast<float4*>(&g_qpart[off]) =
            make_float4(c[i][0], c[i][1], c[i][2], c[i][3]);
    }
}

// ---------------------------------------------------------------------------
// K4: combine k-splits, normalize, G-field, Heun state update.
// ---------------------------------------------------------------------------
__global__ void k_update(float sigmat, int first, int last, float* __restrict__ out) {
    int idx = blockIdx.x * blockDim.x + threadIdx.x;
    if (idx >= Nn * Dd) return;
    int n = idx >> 6;
    float q = (g_qpart[idx] + g_qpart[Nn * Dd + idx] +
               g_qpart[2 * Nn * Dd + idx] + g_qpart[3 * Nn * Dd + idx]) /
              g_rsum[n];
    float xe = g_xeff[idx];
    float G = ((1.f - S0c) * xe - q) / sigmat;
    float xt = g_xt[idx];
    if (!first) {
        xt = xt - (g_G1[idx] + G) * (Hh * 0.5f);
        g_xt[idx] = xt;
    }
    g_G1[idx] = G;
    g_xeff[idx] = xt - Hh * G;   // predictor state for next eval
    if (last) out[idx] = xt;
}

// ---------------------------------------------------------------------------
extern "C" void kernel_launch(void* const* d_in, const int* in_sizes, int n_in,
                              void* d_out, int out_size) {
    const float* z = (const float*)d_in[0];
    const float* x0 = (const float*)d_in[1];

    k_init<<<(Nn * Dd + 255) / 256, 256>>>(z, x0);

    for (int e = 0; e < Tt; e++) {
        float t = (e == 0) ? 1.0f : (float)(Tt - e) / (float)Tt;
        float alphat = 1.0f - t;
        float sigmat = S0c + (1.0f - S0c) * t;
        float inv2s2 = 1.0f / (sigmat * sigmat);
        float scale = alphat * inv2s2;              // coefficient on the dot
        float c2 = 0.5f * alphat * alphat * inv2s2; // coefficient on ||x0||^2

        k_gemm1<<<dim3(32, 32), 256>>>(x0, scale, c2);
        k_rowstats<<<Nn, 128>>>();
        k_gemm2<<<dim3(KSPLIT, 32), 256>>>(x0);
        k_update<<<(Nn * Dd + 255) / 256, 256>>>(sigmat, e == 0, e == Tt - 1,
                                                 (float*)d_out);
    }
}

// round 2
// speedup vs baseline: 1.1535x; 1.1535x over previous
#include <cuda_runtime.h>

// FlowDE: Heun integration of a flow ODE whose drift needs an attention-like
// softmax field per evaluation.
//   logits[n,m] = scale * (x_n . x0_m) - c2 * ||x0_m||^2      (row-const term cancels)
//   qt = softmax(logits) @ x0
//   G  = ((1-S0)*x - qt) / sigma(t)
// 8 G-evaluations total (t = 1, 7/8, ..., 1/8).
//
// R2: KSPLIT 4->16 so k_gemm2 fills the chip (512 blocks vs 128; occ was 12.5%).

#define Nn 4096
#define Mm 4096
#define Dd 64
#define Tt 8
#define Hh 0.125f
#define S0c 0.001f
#define KSPLIT 16

__device__ float g_xt[Nn * Dd];
__device__ float g_xeff[Nn * Dd];
__device__ float g_G1[Nn * Dd];
__device__ float g_x0sq[Mm];
__device__ float g_S[(size_t)Nn * Mm];     // 64 MB logits scratch (fits L2)
__device__ float g_rmax[Nn];
__device__ float g_rsum[Nn];
__device__ float g_qpart[KSPLIT * Nn * Dd];

// ---------------------------------------------------------------------------
// Init: xt = xeff = z; x0sq[m] = ||x0_m||^2
// ---------------------------------------------------------------------------
__global__ void k_init(const float* __restrict__ z, const float* __restrict__ x0) {
    int idx = blockIdx.x * blockDim.x + threadIdx.x;
    if (idx < Nn * Dd) {
        float v = z[idx];
        g_xt[idx] = v;
        g_xeff[idx] = v;
    }
    if (idx < Mm) {
        const float4* r = reinterpret_cast<const float4*>(x0 + idx * Dd);
        float s = 0.f;
#pragma unroll
        for (int i = 0; i < Dd / 4; i++) {
            float4 v = r[i];
            s += v.x * v.x + v.y * v.y + v.z * v.z + v.w * v.w;
        }
        g_x0sq[idx] = s;
    }
}

// ---------------------------------------------------------------------------
// K1: logits = scale * (xeff @ x0^T) - c2 * x0sq.  Block tile 128x128, K=64.
// 256 threads, 8x8 micro-tile. Shared tiles stored K-major (transposed).
// ---------------------------------------------------------------------------
__global__ __launch_bounds__(256) void k_gemm1(const float* __restrict__ x0,
                                               float scale, float c2) {
    __shared__ float XT[32][132];
    __shared__ float X0T[32][132];

    const int tid = threadIdx.x;
    const int n0 = blockIdx.y * 128;
    const int m0 = blockIdx.x * 128;
    const int tn = tid / 16;   // 0..15 -> 8 rows each
    const int tm = tid % 16;   // 0..15 -> 8 cols each
    const int lr = tid / 8;    // loader: 0..31
    const int lq = tid % 8;    // loader: 0..7 (float4 column group)

    float c[8][8];
#pragma unroll
    for (int i = 0; i < 8; i++)
#pragma unroll
        for (int j = 0; j < 8; j++) c[i][j] = 0.f;

    for (int kk = 0; kk < 2; kk++) {
        __syncthreads();
#pragma unroll
        for (int it = 0; it < 4; it++) {
            int r = lr + 32 * it;
            float4 va = *reinterpret_cast<const float4*>(
                &g_xeff[(n0 + r) * Dd + kk * 32 + 4 * lq]);
            XT[4 * lq + 0][r] = va.x;
            XT[4 * lq + 1][r] = va.y;
            XT[4 * lq + 2][r] = va.z;
            XT[4 * lq + 3][r] = va.w;
            float4 vb = *reinterpret_cast<const float4*>(
                &x0[(m0 + r) * Dd + kk * 32 + 4 * lq]);
            X0T[4 * lq + 0][r] = vb.x;
            X0T[4 * lq + 1][r] = vb.y;
            X0T[4 * lq + 2][r] = vb.z;
            X0T[4 * lq + 3][r] = vb.w;
        }
        __syncthreads();
#pragma unroll
        for (int k = 0; k < 32; k++) {
            float4 a0 = *reinterpret_cast<const float4*>(&XT[k][8 * tn]);
            float4 a1 = *reinterpret_cast<const float4*>(&XT[k][8 * tn + 4]);
            float4 b0 = *reinterpret_cast<const float4*>(&X0T[k][8 * tm]);
            float4 b1 = *reinterpret_cast<const float4*>(&X0T[k][8 * tm + 4]);
            float a[8] = {a0.x, a0.y, a0.z, a0.w, a1.x, a1.y, a1.z, a1.w};
            float b[8] = {b0.x, b0.y, b0.z, b0.w, b1.x, b1.y, b1.z, b1.w};
#pragma unroll
            for (int i = 0; i < 8; i++)
#pragma unroll
                for (int j = 0; j < 8; j++) c[i][j] += a[i] * b[j];
        }
    }

    float bias[8];
#pragma unroll
    for (int j = 0; j < 8; j++) bias[j] = -c2 * g_x0sq[m0 + 8 * tm + j];

#pragma unroll
    for (int i = 0; i < 8; i++) {
        size_t off = (size_t)(n0 + 8 * tn + i) * Mm + m0 + 8 * tm;
        float4 w0 = make_float4(fmaf(scale, c[i][0], bias[0]),
                                fmaf(scale, c[i][1], bias[1]),
                                fmaf(scale, c[i][2], bias[2]),
                                fmaf(scale, c[i][3], bias[3]));
        float4 w1 = make_float4(fmaf(scale, c[i][4], bias[4]),
                                fmaf(scale, c[i][5], bias[5]),
                                fmaf(scale, c[i][6], bias[6]),
                                fmaf(scale, c[i][7], bias[7]));
        *reinterpret_cast<float4*>(&g_S[off]) = w0;
        *reinterpret_cast<float4*>(&g_S[off + 4]) = w1;
    }
}

// ---------------------------------------------------------------------------
// K2: per-row online (max, sum of exp) over 4096 logits. One block per row.
// ---------------------------------------------------------------------------
__global__ void k_rowstats() {
    const int n = blockIdx.x;
    const float4* row = reinterpret_cast<const float4*>(&g_S[(size_t)n * Mm]);
    float mx = -1e30f, sm = 0.f;
    for (int i = threadIdx.x; i < Mm / 4; i += 128) {
        float4 v = row[i];
        float vals[4] = {v.x, v.y, v.z, v.w};
#pragma unroll
        for (int j = 0; j < 4; j++) {
            float x = vals[j];
            if (x > mx) {
                sm = sm * __expf(mx - x) + 1.f;
                mx = x;
            } else {
                sm += __expf(x - mx);
            }
        }
    }
#pragma unroll
    for (int o = 16; o; o >>= 1) {
        float mx2 = __shfl_xor_sync(0xffffffffu, mx, o);
        float sm2 = __shfl_xor_sync(0xffffffffu, sm, o);
        float m = fmaxf(mx, mx2);
        sm = sm * __expf(mx - m) + sm2 * __expf(mx2 - m);
        mx = m;
    }
    __shared__ float smx[4], ssm[4];
    int w = threadIdx.x >> 5;
    if ((threadIdx.x & 31) == 0) { smx[w] = mx; ssm[w] = sm; }
    __syncthreads();
    if (threadIdx.x == 0) {
        mx = smx[0]; sm = ssm[0];
#pragma unroll
        for (int w2 = 1; w2 < 4; w2++) {
            float m = fmaxf(mx, smx[w2]);
            sm = sm * __expf(mx - m) + ssm[w2] * __expf(smx[w2] - m);
            mx = m;
        }
        g_rmax[n] = mx;
        g_rsum[n] = sm;
    }
}

// ---------------------------------------------------------------------------
// K3: qpart[s] = exp(S - rmax) @ x0 over m-range [s*256, (s+1)*256).
// Block tile 128n x 64d, k-tiles of 32. 256 threads, 8x4 micro-tile.
// ---------------------------------------------------------------------------
__global__ __launch_bounds__(256) void k_gemm2(const float* __restrict__ x0) {
    __shared__ float PT[32][132];     // exp(logit - rmax), k-major
    __shared__ float X0s[32][Dd];     // x0 tile, row-major
    __shared__ float rm[128];

    const int tid = threadIdx.x;
    const int s = blockIdx.x;          // k-split index
    const int n0 = blockIdx.y * 128;
    const int tn = tid / 16;           // 0..15 -> 8 n-rows
    const int td = tid % 16;           // 0..15 -> 4 d-cols
    const int lr = tid / 8;            // loader 0..31
    const int lq = tid % 8;            // loader 0..7

    if (tid < 128) rm[tid] = g_rmax[n0 + tid];

    float c[8][4];
#pragma unroll
    for (int i = 0; i < 8; i++)
#pragma unroll
        for (int j = 0; j < 4; j++) c[i][j] = 0.f;

    for (int kt = 0; kt < Mm / KSPLIT; kt += 32) {
        const int mb = s * (Mm / KSPLIT) + kt;
        __syncthreads();
#pragma unroll
        for (int it = 0; it < 4; it++) {
            int r = lr + 32 * it;
            float4 v = *reinterpret_cast<const float4*>(
                &g_S[(size_t)(n0 + r) * Mm + mb + 4 * lq]);
            float rmax = rm[r];
            PT[4 * lq + 0][r] = __expf(v.x - rmax);
            PT[4 * lq + 1][r] = __expf(v.y - rmax);
            PT[4 * lq + 2][r] = __expf(v.z - rmax);
            PT[4 * lq + 3][r] = __expf(v.w - rmax);
        }
#pragma unroll
        for (int it = 0; it < 2; it++) {
            int v = tid + 256 * it;          // 0..511 float4 slots (32x16)
            int rr = v / 16, c4 = v % 16;
            *reinterpret_cast<float4*>(&X0s[rr][4 * c4]) =
                *reinterpret_cast<const float4*>(&x0[(mb + rr) * Dd + 4 * c4]);
        }
        __syncthreads();
#pragma unroll
        for (int k = 0; k < 32; k++) {
            float4 a0 = *reinterpret_cast<const float4*>(&PT[k][8 * tn]);
            float4 a1 = *reinterpret_cast<const float4*>(&PT[k][8 * tn + 4]);
            float4 b = *reinterpret_cast<const float4*>(&X0s[k][4 * td]);
            float a[8] = {a0.x, a0.y, a0.z, a0.w, a1.x, a1.y, a1.z, a1.w};
            float bb[4] = {b.x, b.y, b.z, b.w};
#pragma unroll
            for (int i = 0; i < 8; i++)
#pragma unroll
                for (int j = 0; j < 4; j++) c[i][j] += a[i] * bb[j];
        }
    }

#pragma unroll
    for (int i = 0; i < 8; i++) {
        int off = s * Nn * Dd + (n0 + 8 * tn + i) * Dd + 4 * td;
        *reinterpret_cast<float4*>(&g_qpart[off]) =
            make_float4(c[i][0], c[i][1], c[i][2], c[i][3]);
    }
}

// ---------------------------------------------------------------------------
// K4: combine k-splits, normalize, G-field, Heun state update.
// ---------------------------------------------------------------------------
__global__ void k_update(float sigmat, int first, int last, float* __restrict__ out) {
    int idx = blockIdx.x * blockDim.x + threadIdx.x;
    if (idx >= Nn * Dd) return;
    int n = idx >> 6;
    float q = 0.f;
#pragma unroll
    for (int s = 0; s < KSPLIT; s++) q += g_qpart[s * Nn * Dd + idx];
    q /= g_rsum[n];
    float xe = g_xeff[idx];
    float G = ((1.f - S0c) * xe - q) / sigmat;
    float xt = g_xt[idx];
    if (!first) {
        xt = xt - (g_G1[idx] + G) * (Hh * 0.5f);
        g_xt[idx] = xt;
    }
    g_G1[idx] = G;
    g_xeff[idx] = xt - Hh * G;   // predictor state for next eval
    if (last) out[idx] = xt;
}

// ---------------------------------------------------------------------------
extern "C" void kernel_launch(void* const* d_in, const int* in_sizes, int n_in,
                              void* d_out, int out_size) {
    const float* z = (const float*)d_in[0];
    const float* x0 = (const float*)d_in[1];

    k_init<<<(Nn * Dd + 255) / 256, 256>>>(z, x0);

    for (int e = 0; e < Tt; e++) {
        float t = (e == 0) ? 1.0f : (float)(Tt - e) / (float)Tt;
        float alphat = 1.0f - t;
        float sigmat = S0c + (1.0f - S0c) * t;
        float inv2s2 = 1.0f / (sigmat * sigmat);
        float scale = alphat * inv2s2;              // coefficient on the dot
        float c2 = 0.5f * alphat * alphat * inv2s2; // coefficient on ||x0||^2

        k_gemm1<<<dim3(32, 32), 256>>>(x0, scale, c2);
        k_rowstats<<<Nn, 128>>>();
        k_gemm2<<<dim3(KSPLIT, 32), 256>>>(x0);
        k_update<<<(Nn * Dd + 255) / 256, 256>>>(sigmat, e == 0, e == Tt - 1,
                                                 (float*)d_out);
    }
}

// round 3
// speedup vs baseline: 1.2813x; 1.1108x over previous
#include <cuda_runtime.h>

// FlowDE: Heun integration; each G-eval = logits GEMM + softmax + weighted GEMM.
// R3: (a) packed fma.rn.f32x2 in both GEMM inner loops (2 fp32 FMA / instr;
//     ptxas never emits this on its own), (b) row max/sumexp fused into gemm1
//     epilogue as per-block partials + tiny reduce kernel (kills 64MB re-read).

#define Nn 4096
#define Mm 4096
#define Dd 64
#define Tt 8
#define Hh 0.125f
#define S0c 0.001f
#define KSPLIT 16
#define MBLK 32   // number of 128-wide column blocks in gemm1

typedef unsigned long long u64;

__device__ __forceinline__ u64 pack2(float lo, float hi) {
    u64 r;
    asm("mov.b64 %0, {%1, %2};" : "=l"(r) : "f"(lo), "f"(hi));
    return r;
}
__device__ __forceinline__ void unpack2(float& lo, float& hi, u64 v) {
    asm("mov.b64 {%0, %1}, %2;" : "=f"(lo), "=f"(hi) : "l"(v));
}
__device__ __forceinline__ void ffma2(u64& d, u64 a, u64 b) {
    asm("fma.rn.f32x2 %0, %1, %2, %0;" : "+l"(d) : "l"(a), "l"(b));
}

__device__ float g_xt[Nn * Dd];
__device__ float g_xeff[Nn * Dd];
__device__ float g_G1[Nn * Dd];
__device__ float g_x0sq[Mm];
__device__ float g_S[(size_t)Nn * Mm];     // 64 MB logits scratch
__device__ float g_pmax[MBLK * Nn];        // per (m-block, row) partial max
__device__ float g_psum[MBLK * Nn];        // per (m-block, row) partial sumexp
__device__ float g_rmax[Nn];
__device__ float g_rsum[Nn];
__device__ float g_qpart[KSPLIT * Nn * Dd];

// ---------------------------------------------------------------------------
__global__ void k_init(const float* __restrict__ z, const float* __restrict__ x0) {
    int idx = blockIdx.x * blockDim.x + threadIdx.x;
    if (idx < Nn * Dd) {
        float v = z[idx];
        g_xt[idx] = v;
        g_xeff[idx] = v;
    }
    if (idx < Mm) {
        const float4* r = reinterpret_cast<const float4*>(x0 + idx * Dd);
        float s = 0.f;
#pragma unroll
        for (int i = 0; i < Dd / 4; i++) {
            float4 v = r[i];
            s += v.x * v.x + v.y * v.y + v.z * v.z + v.w * v.w;
        }
        g_x0sq[idx] = s;
    }
}

// ---------------------------------------------------------------------------
// K1: logits tile 128x128 (K=64), packed-f32x2 FMA core; epilogue writes
// logits to g_S AND per-block-row (max, sumexp) partials.
// ---------------------------------------------------------------------------
__global__ __launch_bounds__(256) void k_gemm1(const float* __restrict__ x0,
                                               float scale, float c2) {
    __shared__ float XT[32][132];
    __shared__ float X0T[32][132];

    const int tid = threadIdx.x;
    const int n0 = blockIdx.y * 128;
    const int m0 = blockIdx.x * 128;
    const int tn = tid / 16;
    const int tm = tid % 16;
    const int lr = tid / 8;
    const int lq = tid % 8;

    u64 acc[8][4];
#pragma unroll
    for (int i = 0; i < 8; i++)
#pragma unroll
        for (int j = 0; j < 4; j++) acc[i][j] = 0ull;

    for (int kk = 0; kk < 2; kk++) {
        __syncthreads();
#pragma unroll
        for (int it = 0; it < 4; it++) {
            int r = lr + 32 * it;
            float4 va = *reinterpret_cast<const float4*>(
                &g_xeff[(n0 + r) * Dd + kk * 32 + 4 * lq]);
            XT[4 * lq + 0][r] = va.x;
            XT[4 * lq + 1][r] = va.y;
            XT[4 * lq + 2][r] = va.z;
            XT[4 * lq + 3][r] = va.w;
            float4 vb = *reinterpret_cast<const float4*>(
                &x0[(m0 + r) * Dd + kk * 32 + 4 * lq]);
            X0T[4 * lq + 0][r] = vb.x;
            X0T[4 * lq + 1][r] = vb.y;
            X0T[4 * lq + 2][r] = vb.z;
            X0T[4 * lq + 3][r] = vb.w;
        }
        __syncthreads();
#pragma unroll
        for (int k = 0; k < 32; k++) {
            float4 a0 = *reinterpret_cast<const float4*>(&XT[k][8 * tn]);
            float4 a1 = *reinterpret_cast<const float4*>(&XT[k][8 * tn + 4]);
            float4 b0 = *reinterpret_cast<const float4*>(&X0T[k][8 * tm]);
            float4 b1 = *reinterpret_cast<const float4*>(&X0T[k][8 * tm + 4]);
            u64 bp[4] = {pack2(b0.x, b0.y), pack2(b0.z, b0.w),
                         pack2(b1.x, b1.y), pack2(b1.z, b1.w)};
            float a[8] = {a0.x, a0.y, a0.z, a0.w, a1.x, a1.y, a1.z, a1.w};
#pragma unroll
            for (int i = 0; i < 8; i++) {
                u64 ai = pack2(a[i], a[i]);
#pragma unroll
                for (int j = 0; j < 4; j++) ffma2(acc[i][j], ai, bp[j]);
            }
        }
    }

    float bias[8];
#pragma unroll
    for (int j = 0; j < 8; j++) bias[j] = -c2 * g_x0sq[m0 + 8 * tm + j];

    float l[8][8];
#pragma unroll
    for (int i = 0; i < 8; i++) {
#pragma unroll
        for (int j = 0; j < 4; j++) {
            float lo, hi;
            unpack2(lo, hi, acc[i][j]);
            l[i][2 * j] = fmaf(scale, lo, bias[2 * j]);
            l[i][2 * j + 1] = fmaf(scale, hi, bias[2 * j + 1]);
        }
        size_t off = (size_t)(n0 + 8 * tn + i) * Mm + m0 + 8 * tm;
        *reinterpret_cast<float4*>(&g_S[off]) =
            make_float4(l[i][0], l[i][1], l[i][2], l[i][3]);
        *reinterpret_cast<float4*>(&g_S[off + 4]) =
            make_float4(l[i][4], l[i][5], l[i][6], l[i][7]);
    }

    // Per-block-row stats: reduce over 8 local cols, then across the 16 tm
    // lanes (lanes sharing tn live in one 16-lane half-warp).
#pragma unroll
    for (int i = 0; i < 8; i++) {
        float m = l[i][0];
#pragma unroll
        for (int j = 1; j < 8; j++) m = fmaxf(m, l[i][j]);
#pragma unroll
        for (int o = 8; o; o >>= 1)
            m = fmaxf(m, __shfl_xor_sync(0xffffffffu, m, o));
        float s = 0.f;
#pragma unroll
        for (int j = 0; j < 8; j++) s += __expf(l[i][j] - m);
#pragma unroll
        for (int o = 8; o; o >>= 1) s += __shfl_xor_sync(0xffffffffu, s, o);
        if (tm == 0) {
            int n = n0 + 8 * tn + i;
            g_pmax[blockIdx.x * Nn + n] = m;
            g_psum[blockIdx.x * Nn + n] = s;
        }
    }
}

// ---------------------------------------------------------------------------
// K2: combine MBLK partials per row into (rmax, rsum). Coalesced.
// ---------------------------------------------------------------------------
__global__ void k_reduce() {
    int n = blockIdx.x * blockDim.x + threadIdx.x;
    if (n >= Nn) return;
    float mx = -1e30f;
#pragma unroll
    for (int k = 0; k < MBLK; k++) mx = fmaxf(mx, g_pmax[k * Nn + n]);
    float sm = 0.f;
#pragma unroll
    for (int k = 0; k < MBLK; k++)
        sm += g_psum[k * Nn + n] * __expf(g_pmax[k * Nn + n] - mx);
    g_rmax[n] = mx;
    g_rsum[n] = sm;
}

// ---------------------------------------------------------------------------
// K3: qpart[s] = exp(S - rmax) @ x0 over one m-range. Packed-f32x2 core.
// ---------------------------------------------------------------------------
__global__ __launch_bounds__(256) void k_gemm2(const float* __restrict__ x0) {
    __shared__ float PT[32][132];
    __shared__ float X0s[32][Dd];
    __shared__ float rm[128];

    const int tid = threadIdx.x;
    const int s = blockIdx.x;
    const int n0 = blockIdx.y * 128;
    const int tn = tid / 16;
    const int td = tid % 16;
    const int lr = tid / 8;
    const int lq = tid % 8;

    if (tid < 128) rm[tid] = g_rmax[n0 + tid];

    u64 acc[8][2];
#pragma unroll
    for (int i = 0; i < 8; i++) {
        acc[i][0] = 0ull;
        acc[i][1] = 0ull;
    }

    for (int kt = 0; kt < Mm / KSPLIT; kt += 32) {
        const int mb = s * (Mm / KSPLIT) + kt;
        __syncthreads();
#pragma unroll
        for (int it = 0; it < 4; it++) {
            int r = lr + 32 * it;
            float4 v = *reinterpret_cast<const float4*>(
                &g_S[(size_t)(n0 + r) * Mm + mb + 4 * lq]);
            float rmax = rm[r];
            PT[4 * lq + 0][r] = __expf(v.x - rmax);
            PT[4 * lq + 1][r] = __expf(v.y - rmax);
            PT[4 * lq + 2][r] = __expf(v.z - rmax);
            PT[4 * lq + 3][r] = __expf(v.w - rmax);
        }
#pragma unroll
        for (int it = 0; it < 2; it++) {
            int v = tid + 256 * it;
            int rr = v / 16, c4 = v % 16;
            *reinterpret_cast<float4*>(&X0s[rr][4 * c4]) =
                *reinterpret_cast<const float4*>(&x0[(mb + rr) * Dd + 4 * c4]);
        }
        __syncthreads();
#pragma unroll
        for (int k = 0; k < 32; k++) {
            float4 a0 = *reinterpret_cast<const float4*>(&PT[k][8 * tn]);
            float4 a1 = *reinterpret_cast<const float4*>(&PT[k][8 * tn + 4]);
            float4 b = *reinterpret_cast<const float4*>(&X0s[k][4 * td]);
            u64 bp0 = pack2(b.x, b.y);
            u64 bp1 = pack2(b.z, b.w);
            float a[8] = {a0.x, a0.y, a0.z, a0.w, a1.x, a1.y, a1.z, a1.w};
#pragma unroll
            for (int i = 0; i < 8; i++) {
                u64 ai = pack2(a[i], a[i]);
                ffma2(acc[i][0], ai, bp0);
                ffma2(acc[i][1], ai, bp1);
            }
        }
    }

#pragma unroll
    for (int i = 0; i < 8; i++) {
        float c0, c1, c2v, c3;
        unpack2(c0, c1, acc[i][0]);
        unpack2(c2v, c3, acc[i][1]);
        int off = s * Nn * Dd + (n0 + 8 * tn + i) * Dd + 4 * td;
        *reinterpret_cast<float4*>(&g_qpart[off]) = make_float4(c0, c1, c2v, c3);
    }
}

// ---------------------------------------------------------------------------
// K4: combine k-splits, normalize, G-field, Heun state update.
// ---------------------------------------------------------------------------
__global__ void k_update(float sigmat, int first, int last, float* __restrict__ out) {
    int idx = blockIdx.x * blockDim.x + threadIdx.x;
    if (idx >= Nn * Dd) return;
    int n = idx >> 6;
    float q = 0.f;
#pragma unroll
    for (int s = 0; s < KSPLIT; s++) q += g_qpart[s * Nn * Dd + idx];
    q /= g_rsum[n];
    float xe = g_xeff[idx];
    float G = ((1.f - S0c) * xe - q) / sigmat;
    float xt = g_xt[idx];
    if (!first) {
        xt = xt - (g_G1[idx] + G) * (Hh * 0.5f);
        g_xt[idx] = xt;
    }
    g_G1[idx] = G;
    g_xeff[idx] = xt - Hh * G;
    if (last) out[idx] = xt;
}

// ---------------------------------------------------------------------------
extern "C" void kernel_launch(void* const* d_in, const int* in_sizes, int n_in,
                              void* d_out, int out_size) {
    const float* z = (const float*)d_in[0];
    const float* x0 = (const float*)d_in[1];

    k_init<<<(Nn * Dd + 255) / 256, 256>>>(z, x0);

    for (int e = 0; e < Tt; e++) {
        float t = (e == 0) ? 1.0f : (float)(Tt - e) / (float)Tt;
        float alphat = 1.0f - t;
        float sigmat = S0c + (1.0f - S0c) * t;
        float inv2s2 = 1.0f / (sigmat * sigmat);
        float scale = alphat * inv2s2;
        float c2 = 0.5f * alphat * alphat * inv2s2;

        k_gemm1<<<dim3(MBLK, 32), 256>>>(x0, scale, c2);
        k_reduce<<<Nn / 256, 256>>>();
        k_gemm2<<<dim3(KSPLIT, 32), 256>>>(x0);
        k_update<<<(Nn * Dd + 255) / 256, 256>>>(sigmat, e == 0, e == Tt - 1,
                                                 (float*)d_out);
    }
}

// round 5
// speedup vs baseline: 1.2862x; 1.0038x over previous
#include <cuda_runtime.h>
#include <cstdint>

// FlowDE R5: GEMM1 (logits) via mma.sync tf32 (3xTF32 split emulation of fp32).
// tcgen05 is unavailable (harness compiles PTX for generic sm_103 target), but
// base-PTX mma.sync m16n8k8 tf32 works and hits the tensor pipe via HMMA.
//   logits[n,m] = scale * (x_n . x0_m) - c2 * ||x0_m||^2
//   qt = softmax(logits) @ x0 ;  G = ((1-S0)*x - qt)/sigma ;  8 Heun evals.

#define Nn 4096
#define Mm 4096
#define Dd 64
#define Tt 8
#define Hh 0.125f
#define S0c 0.001f
#define KSPLIT 16
#define MBLK 32
#define LDT 36   // smem tile leading dim (conflict-free frag loads)

typedef unsigned long long u64;
typedef uint32_t u32;

// ---------------- f32x2 helpers (gemm2) --------------------------------------
__device__ __forceinline__ u64 pack2(float lo, float hi) {
    u64 r; asm("mov.b64 %0, {%1, %2};" : "=l"(r) : "f"(lo), "f"(hi)); return r;
}
__device__ __forceinline__ void unpack2(float& lo, float& hi, u64 v) {
    asm("mov.b64 {%0, %1}, %2;" : "=f"(lo), "=f"(hi) : "l"(v));
}
__device__ __forceinline__ void ffma2(u64& d, u64 a, u64 b) {
    asm("fma.rn.f32x2 %0, %1, %2, %0;" : "+l"(d) : "l"(a), "l"(b));
}

// ---------------- tf32 helpers ------------------------------------------------
__device__ __forceinline__ u32 to_tf32(float v) {
    u32 r; asm("cvt.rna.tf32.f32 %0, %1;" : "=r"(r) : "f"(v)); return r;
}
__device__ __forceinline__ void mma_tf32(float* d, const u32* a, const u32* b) {
    asm("mma.sync.aligned.m16n8k8.row.col.f32.tf32.tf32.f32 "
        "{%0,%1,%2,%3}, {%4,%5,%6,%7}, {%8,%9}, {%0,%1,%2,%3};"
        : "+f"(d[0]), "+f"(d[1]), "+f"(d[2]), "+f"(d[3])
        : "r"(a[0]), "r"(a[1]), "r"(a[2]), "r"(a[3]), "r"(b[0]), "r"(b[1]));
}

// ---------------- globals -----------------------------------------------------
__device__ float g_xt[Nn * Dd];
__device__ float g_xeff[Nn * Dd];
__device__ float g_G1[Nn * Dd];
__device__ float g_x0sq[Mm];
__device__ float g_S[(size_t)Nn * Mm];
__device__ float g_pmax[MBLK * Nn];
__device__ float g_psum[MBLK * Nn];
__device__ float g_rmax[Nn];
__device__ float g_rsum[Nn];
__device__ float g_qpart[KSPLIT * Nn * Dd];
// tf32 (h,l) splits, stored as f32 bit patterns
__device__ float g_xh32[Nn * Dd], g_xl32[Nn * Dd];
__device__ float g_x0h32[Mm * Dd], g_x0l32[Mm * Dd];

__device__ __forceinline__ void split_tf32(float v, int idx, float* h, float* l) {
    u32 hb = to_tf32(v);
    float hf = __uint_as_float(hb);
    u32 lb = to_tf32(v - hf);
    h[idx] = hf;
    l[idx] = __uint_as_float(lb);
}

// ---------------------------------------------------------------------------
__global__ void k_init(const float* __restrict__ z, const float* __restrict__ x0) {
    int idx = blockIdx.x * blockDim.x + threadIdx.x;
    if (idx < Nn * Dd) {
        float v = z[idx];
        g_xt[idx] = v;
        g_xeff[idx] = v;
        split_tf32(v, idx, g_xh32, g_xl32);
        split_tf32(x0[idx], idx, g_x0h32, g_x0l32);
    }
    if (idx < Mm) {
        const float4* r = reinterpret_cast<const float4*>(x0 + idx * Dd);
        float s = 0.f;
#pragma unroll
        for (int i = 0; i < Dd / 4; i++) {
            float4 v = r[i];
            s += v.x * v.x + v.y * v.y + v.z * v.z + v.w * v.w;
        }
        g_x0sq[idx] = s;
    }
}

// ---------------------------------------------------------------------------
// K1: 128x128 logits tile via mma.sync tf32, 3 products (hh, hl, lh).
// 256 threads = 8 warps, warp grid 4(rows) x 2(cols), warp tile 32x64.
// SMEM: [0,512) x0sq, [1024,2048) pm, [2048,3072) ps,
//       [4096, 4096+4*128*LDT*4) tiles Ah|Al|Bh|Bl (aliased by f32 stage later).
// ---------------------------------------------------------------------------
extern __shared__ char dsm[];

__global__ __launch_bounds__(256) void k_gemm1_mma(float scale, float c2) {
    const int tid = threadIdx.x;
    const int m0 = blockIdx.x * 128;
    const int n0 = blockIdx.y * 128;

    float* x0sq_s = reinterpret_cast<float*>(dsm);
    float* pm = reinterpret_cast<float*>(dsm + 1024);
    float* ps = reinterpret_cast<float*>(dsm + 2048);
    u32* tiles = reinterpret_cast<u32*>(dsm + 4096);
    u32* Ah = tiles;
    u32* Al = tiles + 128 * LDT;
    u32* Bh = tiles + 2 * 128 * LDT;
    u32* Bl = tiles + 3 * 128 * LDT;
    float* stage = reinterpret_cast<float*>(dsm + 4096);  // alias (post-mma)

    const int wid = tid >> 5;
    const int lane = tid & 31;
    const int wr = wid >> 1;      // 0..3 warp row
    const int wc = wid & 1;       // 0..1 warp col
    const int g = lane >> 2;      // group id 0..7
    const int tg = lane & 3;      // thread in group

    if (tid < 128) x0sq_s[tid] = g_x0sq[m0 + tid];

    float c[2][8][4];
#pragma unroll
    for (int rf = 0; rf < 2; rf++)
#pragma unroll
        for (int cm = 0; cm < 8; cm++)
#pragma unroll
            for (int e = 0; e < 4; e++) c[rf][cm][e] = 0.f;

    const float* srcs[4] = {g_xh32 + (size_t)n0 * Dd, g_xl32 + (size_t)n0 * Dd,
                            g_x0h32 + (size_t)m0 * Dd, g_x0l32 + (size_t)m0 * Dd};

    for (int kk = 0; kk < 2; kk++) {
        __syncthreads();
#pragma unroll
        for (int t = 0; t < 4; t++) {
            u32* tb = tiles + t * 128 * LDT;
            const float* src = srcs[t];
#pragma unroll
            for (int it = 0; it < 4; it++) {
                int idx = tid + 256 * it;        // 0..1023
                int row = idx >> 3, q = idx & 7; // 8 float4 per row
                float4 v = *reinterpret_cast<const float4*>(
                    &src[row * Dd + kk * 32 + 4 * q]);
                *reinterpret_cast<float4*>(&tb[row * LDT + 4 * q]) = v;
            }
        }
        __syncthreads();

#pragma unroll
        for (int ks = 0; ks < 4; ks++) {
            u32 ah[2][4], al[2][4];
#pragma unroll
            for (int rf = 0; rf < 2; rf++) {
                int rb = 32 * wr + 16 * rf;
                int co = 8 * ks + tg;
                ah[rf][0] = Ah[(rb + g) * LDT + co];
                ah[rf][1] = Ah[(rb + g + 8) * LDT + co];
                ah[rf][2] = Ah[(rb + g) * LDT + co + 4];
                ah[rf][3] = Ah[(rb + g + 8) * LDT + co + 4];
                al[rf][0] = Al[(rb + g) * LDT + co];
                al[rf][1] = Al[(rb + g + 8) * LDT + co];
                al[rf][2] = Al[(rb + g) * LDT + co + 4];
                al[rf][3] = Al[(rb + g + 8) * LDT + co + 4];
            }
#pragma unroll
            for (int cm = 0; cm < 8; cm++) {
                int cb = 64 * wc + 8 * cm;
                int co = 8 * ks + tg;
                u32 bh[2], bl[2];
                bh[0] = Bh[(cb + g) * LDT + co];
                bh[1] = Bh[(cb + g) * LDT + co + 4];
                bl[0] = Bl[(cb + g) * LDT + co];
                bl[1] = Bl[(cb + g) * LDT + co + 4];
#pragma unroll
                for (int rf = 0; rf < 2; rf++) {
                    mma_tf32(c[rf][cm], ah[rf], bh);
                    mma_tf32(c[rf][cm], ah[rf], bl);
                    mma_tf32(c[rf][cm], al[rf], bh);
                }
            }
        }
    }

    __syncthreads();   // tiles consumed; stage may alias them now

    // epilogue: bias+scale, write stage, per-row (max,sumexp) partials
#pragma unroll
    for (int rf = 0; rf < 2; rf++) {
#pragma unroll
        for (int rh = 0; rh < 2; rh++) {
            int row = 32 * wr + 16 * rf + 8 * rh + g;
            float mx = -1e30f, sm = 0.f;
            float vals[16];
#pragma unroll
            for (int cm = 0; cm < 8; cm++) {
                int col = 64 * wc + 8 * cm + 2 * tg;
                float l0 = fmaf(scale, c[rf][cm][2 * rh], -c2 * x0sq_s[col]);
                float l1 = fmaf(scale, c[rf][cm][2 * rh + 1], -c2 * x0sq_s[col + 1]);
                *reinterpret_cast<float2*>(&stage[row * 132 + col]) =
                    make_float2(l0, l1);
                vals[2 * cm] = l0;
                vals[2 * cm + 1] = l1;
                mx = fmaxf(mx, fmaxf(l0, l1));
            }
#pragma unroll
            for (int e = 0; e < 16; e++) sm += __expf(vals[e] - mx);
#pragma unroll
            for (int o = 1; o <= 2; o <<= 1) {
                float mx2 = __shfl_xor_sync(0xffffffffu, mx, o);
                float sm2 = __shfl_xor_sync(0xffffffffu, sm, o);
                float m = fmaxf(mx, mx2);
                sm = sm * __expf(mx - m) + sm2 * __expf(mx2 - m);
                mx = m;
            }
            if (tg == 0) {
                pm[row * 2 + wc] = mx;
                ps[row * 2 + wc] = sm;
            }
        }
    }
    __syncthreads();

    if (tid < 128) {
        float m0v = pm[tid * 2], m1v = pm[tid * 2 + 1];
        float M = fmaxf(m0v, m1v);
        float s = ps[tid * 2] * __expf(m0v - M) + ps[tid * 2 + 1] * __expf(m1v - M);
        g_pmax[blockIdx.x * Nn + n0 + tid] = M;
        g_psum[blockIdx.x * Nn + n0 + tid] = s;
    }

#pragma unroll
    for (int it = 0; it < 16; it++) {
        int lin = tid + 256 * it;           // 0..4095
        int r2 = lin >> 5, c4 = lin & 31;
        float4 v = *reinterpret_cast<const float4*>(&stage[r2 * 132 + 4 * c4]);
        *reinterpret_cast<float4*>(&g_S[(size_t)(n0 + r2) * Mm + m0 + 4 * c4]) = v;
    }
}

// ---------------------------------------------------------------------------
__global__ void k_reduce() {
    int n = blockIdx.x * blockDim.x + threadIdx.x;
    if (n >= Nn) return;
    float mx = -1e30f;
#pragma unroll
    for (int k = 0; k < MBLK; k++) mx = fmaxf(mx, g_pmax[k * Nn + n]);
    float sm = 0.f;
#pragma unroll
    for (int k = 0; k < MBLK; k++)
        sm += g_psum[k * Nn + n] * __expf(g_pmax[k * Nn + n] - mx);
    g_rmax[n] = mx;
    g_rsum[n] = sm;
}

// ---------------------------------------------------------------------------
__global__ __launch_bounds__(256) void k_gemm2(const float* __restrict__ x0) {
    __shared__ float PT[32][132];
    __shared__ float X0s[32][Dd];
    __shared__ float rm[128];

    const int tid = threadIdx.x;
    const int s = blockIdx.x;
    const int n0 = blockIdx.y * 128;
    const int tn = tid / 16;
    const int td = tid % 16;
    const int lr = tid / 8;
    const int lq = tid % 8;

    if (tid < 128) rm[tid] = g_rmax[n0 + tid];

    u64 acc[8][2];
#pragma unroll
    for (int i = 0; i < 8; i++) { acc[i][0] = 0ull; acc[i][1] = 0ull; }

    for (int kt = 0; kt < Mm / KSPLIT; kt += 32) {
        const int mb = s * (Mm / KSPLIT) + kt;
        __syncthreads();
#pragma unroll
        for (int it = 0; it < 4; it++) {
            int r = lr + 32 * it;
            float4 v = *reinterpret_cast<const float4*>(
                &g_S[(size_t)(n0 + r) * Mm + mb + 4 * lq]);
            float rmax = rm[r];
            PT[4 * lq + 0][r] = __expf(v.x - rmax);
            PT[4 * lq + 1][r] = __expf(v.y - rmax);
            PT[4 * lq + 2][r] = __expf(v.z - rmax);
            PT[4 * lq + 3][r] = __expf(v.w - rmax);
        }
#pragma unroll
        for (int it = 0; it < 2; it++) {
            int v = tid + 256 * it;
            int rr = v / 16, c4 = v % 16;
            *reinterpret_cast<float4*>(&X0s[rr][4 * c4]) =
                *reinterpret_cast<const float4*>(&x0[(mb + rr) * Dd + 4 * c4]);
        }
        __syncthreads();
#pragma unroll
        for (int k = 0; k < 32; k++) {
            float4 a0 = *reinterpret_cast<const float4*>(&PT[k][8 * tn]);
            float4 a1 = *reinterpret_cast<const float4*>(&PT[k][8 * tn + 4]);
            float4 b = *reinterpret_cast<const float4*>(&X0s[k][4 * td]);
            u64 bp0 = pack2(b.x, b.y);
            u64 bp1 = pack2(b.z, b.w);
            float a[8] = {a0.x, a0.y, a0.z, a0.w, a1.x, a1.y, a1.z, a1.w};
#pragma unroll
            for (int i = 0; i < 8; i++) {
                u64 ai = pack2(a[i], a[i]);
                ffma2(acc[i][0], ai, bp0);
                ffma2(acc[i][1], ai, bp1);
            }
        }
    }

#pragma unroll
    for (int i = 0; i < 8; i++) {
        float c0, c1, c2v, c3;
        unpack2(c0, c1, acc[i][0]);
        unpack2(c2v, c3, acc[i][1]);
        int off = s * Nn * Dd + (n0 + 8 * tn + i) * Dd + 4 * td;
        *reinterpret_cast<float4*>(&g_qpart[off]) = make_float4(c0, c1, c2v, c3);
    }
}

// ---------------------------------------------------------------------------
__global__ void k_update(float sigmat, int first, int last, float* __restrict__ out) {
    int idx = blockIdx.x * blockDim.x + threadIdx.x;
    if (idx >= Nn * Dd) return;
    int n = idx >> 6;
    float q = 0.f;
#pragma unroll
    for (int s = 0; s < KSPLIT; s++) q += g_qpart[s * Nn * Dd + idx];
    q /= g_rsum[n];
    float xe = g_xeff[idx];
    float G = ((1.f - S0c) * xe - q) / sigmat;
    float xt = g_xt[idx];
    if (!first) {
        xt = xt - (g_G1[idx] + G) * (Hh * 0.5f);
        g_xt[idx] = xt;
    }
    g_G1[idx] = G;
    float xe2 = xt - Hh * G;
    g_xeff[idx] = xe2;
    split_tf32(xe2, idx, g_xh32, g_xl32);
    if (last) out[idx] = xt;
}

// ---------------------------------------------------------------------------
extern "C" void kernel_launch(void* const* d_in, const int* in_sizes, int n_in,
                              void* d_out, int out_size) {
    const float* z = (const float*)d_in[0];
    const float* x0 = (const float*)d_in[1];

    const int SMEM_G1 = 4096 + 4 * 128 * LDT * 4;   // 77824
    cudaFuncSetAttribute(k_gemm1_mma, cudaFuncAttributeMaxDynamicSharedMemorySize,
                         SMEM_G1);

    k_init<<<(Nn * Dd + 255) / 256, 256>>>(z, x0);

    for (int e = 0; e < Tt; e++) {
        float t = (e == 0) ? 1.0f : (float)(Tt - e) / (float)Tt;
        float alphat = 1.0f - t;
        float sigmat = S0c + (1.0f - S0c) * t;
        float inv2s2 = 1.0f / (sigmat * sigmat);
        float scale = alphat * inv2s2;
        float c2 = 0.5f * alphat * alphat * inv2s2;

        k_gemm1_mma<<<dim3(MBLK, 32), 256, SMEM_G1>>>(scale, c2);
        k_reduce<<<Nn / 256, 256>>>();
        k_gemm2<<<dim3(KSPLIT, 32), 256>>>(x0);
        k_update<<<(Nn * Dd + 255) / 256, 256>>>(sigmat, e == 0, e == Tt - 1,
                                                 (float*)d_out);
    }
}

// round 6
// speedup vs baseline: 1.7751x; 1.3802x over previous
#include <cuda_runtime.h>
#include <cstdint>

// FlowDE R6: fully fused flash-style eval. Per block (m-block 128 x n-tile 128):
//   1) logits = scale*(x.x0^T) - c2*||x0||^2 via 3xTF32 mma.sync
//   2) block-local row max M, P~ = exp(l - M) written transposed to SMEM
//   3) PV: qpart = P~ @ x0 via f32x2 scalar loop (SMEM-only operands)
//   4) partials (pmax,psum,qpart) combined by k_reduce / k_update (split-softmax)
// No 64MB logits scratch in GMEM at all.

#define Nn 4096
#define Mm 4096
#define Dd 64
#define Tt 8
#define Hh 0.125f
#define S0c 0.001f
#define MBLK 32
#define LDT 36    // tf32 tile leading dim
#define LDS_ 132  // P~^T leading dim
#define LDX 68    // x0 f32 tile leading dim

typedef unsigned long long u64;
typedef uint32_t u32;

__device__ __forceinline__ u64 pack2(float lo, float hi) {
    u64 r; asm("mov.b64 %0, {%1, %2};" : "=l"(r) : "f"(lo), "f"(hi)); return r;
}
__device__ __forceinline__ void unpack2(float& lo, float& hi, u64 v) {
    asm("mov.b64 {%0, %1}, %2;" : "=f"(lo), "=f"(hi) : "l"(v));
}
__device__ __forceinline__ void ffma2(u64& d, u64 a, u64 b) {
    asm("fma.rn.f32x2 %0, %1, %2, %0;" : "+l"(d) : "l"(a), "l"(b));
}
__device__ __forceinline__ u32 to_tf32(float v) {
    u32 r; asm("cvt.rna.tf32.f32 %0, %1;" : "=r"(r) : "f"(v)); return r;
}
__device__ __forceinline__ void mma_tf32(float* d, const u32* a, const u32* b) {
    asm("mma.sync.aligned.m16n8k8.row.col.f32.tf32.tf32.f32 "
        "{%0,%1,%2,%3}, {%4,%5,%6,%7}, {%8,%9}, {%0,%1,%2,%3};"
        : "+f"(d[0]), "+f"(d[1]), "+f"(d[2]), "+f"(d[3])
        : "r"(a[0]), "r"(a[1]), "r"(a[2]), "r"(a[3]), "r"(b[0]), "r"(b[1]));
}

// ---------------- globals -----------------------------------------------------
__device__ float g_xt[Nn * Dd];
__device__ float g_xeff[Nn * Dd];
__device__ float g_G1[Nn * Dd];
__device__ float g_x0sq[Mm];
__device__ float g_pmax[MBLK * Nn];
__device__ float g_psum[MBLK * Nn];
__device__ float g_rmax[Nn];
__device__ float g_rsum[Nn];
__device__ float g_qpart[(size_t)MBLK * Nn * Dd];   // 32MB
__device__ float g_xh32[Nn * Dd], g_xl32[Nn * Dd];
__device__ float g_x0h32[Mm * Dd], g_x0l32[Mm * Dd];

__device__ __forceinline__ void split_tf32(float v, int idx, float* h, float* l) {
    u32 hb = to_tf32(v);
    float hf = __uint_as_float(hb);
    u32 lb = to_tf32(v - hf);
    h[idx] = hf;
    l[idx] = __uint_as_float(lb);
}

// ---------------------------------------------------------------------------
__global__ void k_init(const float* __restrict__ z, const float* __restrict__ x0) {
    int idx = blockIdx.x * blockDim.x + threadIdx.x;
    if (idx < Nn * Dd) {
        float v = z[idx];
        g_xt[idx] = v;
        g_xeff[idx] = v;
        split_tf32(v, idx, g_xh32, g_xl32);
        split_tf32(x0[idx], idx, g_x0h32, g_x0l32);
    }
    if (idx < Mm) {
        const float4* r = reinterpret_cast<const float4*>(x0 + idx * Dd);
        float s = 0.f;
#pragma unroll
        for (int i = 0; i < Dd / 4; i++) {
            float4 v = r[i];
            s += v.x * v.x + v.y * v.y + v.z * v.z + v.w * v.w;
        }
        g_x0sq[idx] = s;
    }
}

// ---------------------------------------------------------------------------
// Fused eval kernel. SMEM map (dynamic):
//  [0,512)        x0sq tile
//  [1024,2048)    pm [128][2]
//  [2048,3072)    ps [128][2]
//  [4096,77824)   tf32 tiles Ah|Al|Bh|Bl   (aliased by P~^T [128][LDS_] after mma)
//  [77824,112640) x0 f32 tile [128][LDX]
// ---------------------------------------------------------------------------
extern __shared__ char dsm[];

__global__ __launch_bounds__(256) void k_fused(const float* __restrict__ x0,
                                               float scale, float c2) {
    const int tid = threadIdx.x;
    const int m0 = blockIdx.x * 128;   // m-block
    const int n0 = blockIdx.y * 128;   // n-tile

    float* x0sq_s = reinterpret_cast<float*>(dsm);
    float* pm = reinterpret_cast<float*>(dsm + 1024);
    float* ps = reinterpret_cast<float*>(dsm + 2048);
    u32* tiles = reinterpret_cast<u32*>(dsm + 4096);
    u32* Ah = tiles;
    u32* Al = tiles + 128 * LDT;
    u32* Bh = tiles + 2 * 128 * LDT;
    u32* Bl = tiles + 3 * 128 * LDT;
    float* PT = reinterpret_cast<float*>(dsm + 4096);        // alias, P~^T
    float* X0f = reinterpret_cast<float*>(dsm + 77824);

    const int wid = tid >> 5;
    const int lane = tid & 31;
    const int wr = wid >> 1;
    const int wc = wid & 1;
    const int g = lane >> 2;
    const int tg = lane & 3;

    if (tid < 128) x0sq_s[tid] = g_x0sq[m0 + tid];

    // x0 f32 tile for PV
#pragma unroll
    for (int it = 0; it < 8; it++) {
        int idx = tid + 256 * it;          // 0..2047 float4 slots
        int row = idx >> 4, q = idx & 15;
        float4 v = *reinterpret_cast<const float4*>(&x0[(m0 + row) * Dd + 4 * q]);
        *reinterpret_cast<float4*>(&X0f[row * LDX + 4 * q]) = v;
    }

    float c[2][8][4];
#pragma unroll
    for (int rf = 0; rf < 2; rf++)
#pragma unroll
        for (int cm = 0; cm < 8; cm++)
#pragma unroll
            for (int e = 0; e < 4; e++) c[rf][cm][e] = 0.f;

    const float* srcs[4] = {g_xh32 + (size_t)n0 * Dd, g_xl32 + (size_t)n0 * Dd,
                            g_x0h32 + (size_t)m0 * Dd, g_x0l32 + (size_t)m0 * Dd};

    for (int kk = 0; kk < 2; kk++) {
        __syncthreads();
#pragma unroll
        for (int t = 0; t < 4; t++) {
            u32* tb = tiles + t * 128 * LDT;
            const float* src = srcs[t];
#pragma unroll
            for (int it = 0; it < 4; it++) {
                int idx = tid + 256 * it;
                int row = idx >> 3, q = idx & 7;
                float4 v = *reinterpret_cast<const float4*>(
                    &src[row * Dd + kk * 32 + 4 * q]);
                *reinterpret_cast<float4*>(&tb[row * LDT + 4 * q]) = v;
            }
        }
        __syncthreads();

#pragma unroll
        for (int ks = 0; ks < 4; ks++) {
            u32 ah[2][4], al[2][4];
#pragma unroll
            for (int rf = 0; rf < 2; rf++) {
                int rb = 32 * wr + 16 * rf;
                int co = 8 * ks + tg;
                ah[rf][0] = Ah[(rb + g) * LDT + co];
                ah[rf][1] = Ah[(rb + g + 8) * LDT + co];
                ah[rf][2] = Ah[(rb + g) * LDT + co + 4];
                ah[rf][3] = Ah[(rb + g + 8) * LDT + co + 4];
                al[rf][0] = Al[(rb + g) * LDT + co];
                al[rf][1] = Al[(rb + g + 8) * LDT + co];
                al[rf][2] = Al[(rb + g) * LDT + co + 4];
                al[rf][3] = Al[(rb + g + 8) * LDT + co + 4];
            }
#pragma unroll
            for (int cm = 0; cm < 8; cm++) {
                int cb = 64 * wc + 8 * cm;
                int co = 8 * ks + tg;
                u32 bh[2], bl[2];
                bh[0] = Bh[(cb + g) * LDT + co];
                bh[1] = Bh[(cb + g) * LDT + co + 4];
                bl[0] = Bl[(cb + g) * LDT + co];
                bl[1] = Bl[(cb + g) * LDT + co + 4];
#pragma unroll
                for (int rf = 0; rf < 2; rf++) {
                    mma_tf32(c[rf][cm], ah[rf], bh);
                    mma_tf32(c[rf][cm], ah[rf], bl);
                    mma_tf32(c[rf][cm], al[rf], bh);
                }
            }
        }
    }

    // ---- logits in regs; finish bias, get per-half row max ----
    float lg[2][2][16];   // [rf][rh][16 cols]
#pragma unroll
    for (int rf = 0; rf < 2; rf++) {
#pragma unroll
        for (int rh = 0; rh < 2; rh++) {
            float mx = -1e30f;
#pragma unroll
            for (int cm = 0; cm < 8; cm++) {
                int col = 64 * wc + 8 * cm + 2 * tg;
                float l0 = fmaf(scale, c[rf][cm][2 * rh], -c2 * x0sq_s[col]);
                float l1 = fmaf(scale, c[rf][cm][2 * rh + 1], -c2 * x0sq_s[col + 1]);
                lg[rf][rh][2 * cm] = l0;
                lg[rf][rh][2 * cm + 1] = l1;
                mx = fmaxf(mx, fmaxf(l0, l1));
            }
#pragma unroll
            for (int o = 1; o <= 2; o <<= 1)
                mx = fmaxf(mx, __shfl_xor_sync(0xffffffffu, mx, o));
            if (tg == 0) {
                int row = 32 * wr + 16 * rf + 8 * rh + g;
                pm[row * 2 + wc] = mx;
            }
        }
    }
    __syncthreads();   // pm complete; tiles consumed -> PT aliasing safe below

    // ---- exp with full-row max, write P~^T, accumulate row sums ----
#pragma unroll
    for (int rf = 0; rf < 2; rf++) {
#pragma unroll
        for (int rh = 0; rh < 2; rh++) {
            int row = 32 * wr + 16 * rf + 8 * rh + g;
            float M = fmaxf(pm[row * 2], pm[row * 2 + 1]);
            float sm = 0.f;
#pragma unroll
            for (int cm = 0; cm < 8; cm++) {
                int col = 64 * wc + 8 * cm + 2 * tg;
                float e0 = __expf(lg[rf][rh][2 * cm] - M);
                float e1 = __expf(lg[rf][rh][2 * cm + 1] - M);
                PT[col * LDS_ + row] = e0;
                PT[(col + 1) * LDS_ + row] = e1;
                sm += e0 + e1;
            }
#pragma unroll
            for (int o = 1; o <= 2; o <<= 1)
                sm += __shfl_xor_sync(0xffffffffu, sm, o);
            if (tg == 0) ps[row * 2 + wc] = sm;
        }
    }
    __syncthreads();

    if (tid < 128) {
        float M = fmaxf(pm[tid * 2], pm[tid * 2 + 1]);
        g_pmax[blockIdx.x * Nn + n0 + tid] = M;
        g_psum[blockIdx.x * Nn + n0 + tid] = ps[tid * 2] + ps[tid * 2 + 1];
    }

    // ---- PV: qpart = P~ @ x0  (128n x 64d, k=128m) ----
    const int tn = tid / 16;
    const int td = tid % 16;
    u64 acc[8][2];
#pragma unroll
    for (int i = 0; i < 8; i++) { acc[i][0] = 0ull; acc[i][1] = 0ull; }

#pragma unroll 4
    for (int k = 0; k < 128; k++) {
        float4 a0 = *reinterpret_cast<const float4*>(&PT[k * LDS_ + 8 * tn]);
        float4 a1 = *reinterpret_cast<const float4*>(&PT[k * LDS_ + 8 * tn + 4]);
        float4 b = *reinterpret_cast<const float4*>(&X0f[k * LDX + 4 * td]);
        u64 bp0 = pack2(b.x, b.y);
        u64 bp1 = pack2(b.z, b.w);
        float a[8] = {a0.x, a0.y, a0.z, a0.w, a1.x, a1.y, a1.z, a1.w};
#pragma unroll
        for (int i = 0; i < 8; i++) {
            u64 ai = pack2(a[i], a[i]);
            ffma2(acc[i][0], ai, bp0);
            ffma2(acc[i][1], ai, bp1);
        }
    }

#pragma unroll
    for (int i = 0; i < 8; i++) {
        float c0, c1, c2v, c3;
        unpack2(c0, c1, acc[i][0]);
        unpack2(c2v, c3, acc[i][1]);
        size_t off = (size_t)blockIdx.x * Nn * Dd + (n0 + 8 * tn + i) * Dd + 4 * td;
        *reinterpret_cast<float4*>(&g_qpart[off]) = make_float4(c0, c1, c2v, c3);
    }
}

// ---------------------------------------------------------------------------
__global__ void k_reduce() {
    int n = blockIdx.x * blockDim.x + threadIdx.x;
    if (n >= Nn) return;
    float mx = -1e30f;
#pragma unroll
    for (int k = 0; k < MBLK; k++) mx = fmaxf(mx, g_pmax[k * Nn + n]);
    float sm = 0.f;
#pragma unroll
    for (int k = 0; k < MBLK; k++)
        sm += g_psum[k * Nn + n] * __expf(g_pmax[k * Nn + n] - mx);
    g_rmax[n] = mx;
    g_rsum[n] = sm;
}

// ---------------------------------------------------------------------------
__global__ void k_update(float sigmat, int first, int last, float* __restrict__ out) {
    int idx = blockIdx.x * blockDim.x + threadIdx.x;
    if (idx >= Nn * Dd) return;
    int n = idx >> 6;
    float rmax = g_rmax[n];
    float q = 0.f;
#pragma unroll
    for (int s = 0; s < MBLK; s++) {
        float ef = __expf(g_pmax[s * Nn + n] - rmax);
        q = fmaf(g_qpart[(size_t)s * Nn * Dd + idx], ef, q);
    }
    q /= g_rsum[n];
    float xe = g_xeff[idx];
    float G = ((1.f - S0c) * xe - q) / sigmat;
    float xt = g_xt[idx];
    if (!first) {
        xt = xt - (g_G1[idx] + G) * (Hh * 0.5f);
        g_xt[idx] = xt;
    }
    g_G1[idx] = G;
    float xe2 = xt - Hh * G;
    g_xeff[idx] = xe2;
    split_tf32(xe2, idx, g_xh32, g_xl32);
    if (last) out[idx] = xt;
}

// ---------------------------------------------------------------------------
extern "C" void kernel_launch(void* const* d_in, const int* in_sizes, int n_in,
                              void* d_out, int out_size) {
    const float* z = (const float*)d_in[0];
    const float* x0 = (const float*)d_in[1];

    const int SMEM_F = 77824 + 128 * LDX * 4;   // 112640
    cudaFuncSetAttribute(k_fused, cudaFuncAttributeMaxDynamicSharedMemorySize,
                         SMEM_F);

    k_init<<<(Nn * Dd + 255) / 256, 256>>>(z, x0);

    for (int e = 0; e < Tt; e++) {
        float t = (e == 0) ? 1.0f : (float)(Tt - e) / (float)Tt;
        float alphat = 1.0f - t;
        float sigmat = S0c + (1.0f - S0c) * t;
        float inv2s2 = 1.0f / (sigmat * sigmat);
        float scale = alphat * inv2s2;
        float c2 = 0.5f * alphat * alphat * inv2s2;

        k_fused<<<dim3(MBLK, 32), 256, SMEM_F>>>(x0, scale, c2);
        k_reduce<<<Nn / 256, 256>>>();
        k_update<<<(Nn * Dd + 255) / 256, 256>>>(sigmat, e == 0, e == Tt - 1,
                                                 (float*)d_out);
    }
}